// round 15
// baseline (speedup 1.0000x reference)
#include <cuda_runtime.h>
#include <cstddef>

#define NSTEPS 16
#define BMAX   131072
#define ELEMS  96
#define TPB    192

typedef unsigned long long ull;

// Per-batch folded Z weights (20 ull pairs, layout p*B + b), L2-resident stream
__device__ float g_Zw[40 * BMAX];
// Per-batch eps pairs, transposed: g_vp[p*B + b] = pack(v[2p], v[2p+1])
__device__ ull   g_vp[32 * BMAX];

// ---------------- f32x2 helpers ----------------
__device__ __forceinline__ ull f2fma(ull a, ull b, ull c) {
    ull d;
    asm("fma.rn.f32x2 %0, %1, %2, %3;" : "=l"(d) : "l"(a), "l"(b), "l"(c));
    return d;
}
__device__ __forceinline__ ull dupf(float s) {
    ull d; asm("mov.b64 %0, {%1, %1};" : "=l"(d) : "f"(s)); return d;
}
__device__ __forceinline__ ull dup_lo(ull p) {
    ull d;
    asm("{\n\t.reg .f32 l,h;\n\tmov.b64 {l,h}, %1;\n\tmov.b64 %0, {l,l};\n\t}"
        : "=l"(d) : "l"(p));
    return d;
}
__device__ __forceinline__ ull dup_hi(ull p) {
    ull d;
    asm("{\n\t.reg .f32 l,h;\n\tmov.b64 {l,h}, %1;\n\tmov.b64 %0, {h,h};\n\t}"
        : "=l"(d) : "l"(p));
    return d;
}
__device__ __forceinline__ float hadd(ull p) {
    float l, h; asm("mov.b64 {%0, %1}, %2;" : "=f"(l), "=f"(h) : "l"(p)); return l + h;
}
__device__ __forceinline__ ull pack2(float a, float b) {
    ull d; asm("mov.b64 %0, {%1, %2};" : "=l"(d) : "f"(a), "f"(b)); return d;
}
__device__ __forceinline__ ull dup_elem(const ull* base, int k) {
    return (k & 1) ? dup_hi(base[k >> 1]) : dup_lo(base[k >> 1]);
}
__device__ __forceinline__ constexpr int fidx(int i, int j) {
    return i * 8 - i * (i + 1) / 2 + (j - i - 1);
}

// smem: 3 stage buffers + sv (all ull[32*ELEMS]) + weights
#define SMEM_BYTES (4*32*ELEMS*8 + 64*8 + 128*4)

// ---------------------------------------------------------------------------
// Precompute per-batch data: g_vp (eps pairs transposed) and g_Zw (folded
// Z = C W2 - W2 C weights, C = v^T v, for the 20 S-pairs).
// ---------------------------------------------------------------------------
__global__ void precompute_kernel(const float* __restrict__ eps,
                                  const float* __restrict__ W2, int B) {
    int b = blockIdx.x * blockDim.x + threadIdx.x;
    if (b >= B) return;

    float v[64];
    const float4* vp = reinterpret_cast<const float4*>(eps + (size_t)b * 64);
#pragma unroll
    for (int i = 0; i < 16; i++) {
        float4 t = __ldg(vp + i);
        v[4*i+0] = t.x; v[4*i+1] = t.y; v[4*i+2] = t.z; v[4*i+3] = t.w;
    }
#pragma unroll
    for (int p = 0; p < 32; p++)
        g_vp[(size_t)p * B + b] = pack2(v[2*p], v[2*p+1]);

    float C[8][8];
#pragma unroll
    for (int i = 0; i < 8; i++) {
#pragma unroll
        for (int j = i; j < 8; j++) {
            float s = 0.f;
#pragma unroll
            for (int k = 0; k < 8; k++) s = fmaf(v[k*8+i], v[k*8+j], s);
            C[i][j] = s; C[j][i] = s;
        }
    }

    float w2a[8][8];
#pragma unroll
    for (int i = 0; i < 8; i++)
#pragma unroll
        for (int j = 0; j < 8; j++)
            w2a[i][j] = __ldg(W2 + i*8 + j) - __ldg(W2 + j*8 + i);

    int p = 0;
#pragma unroll
    for (int i = 0; i < 8; i++) {
#pragma unroll
        for (int jj = 0; jj < 4; jj++) {
            if (jj < i / 2) continue;
            float wpair[2];
#pragma unroll
            for (int h = 0; h < 2; h++) {
                int j = 2*jj + h;
                float s = 0.f;
                if (j > i) {
#pragma unroll
                    for (int k = 0; k < 8; k++)
                        s -= C[i][k] * w2a[j][k] + C[j][k] * w2a[i][k];
                } else if (j == i) {
#pragma unroll
                    for (int k = 0; k < 8; k++) s -= C[i][k] * w2a[i][k];
                }
                wpair[h] = s;
            }
            g_Zw[((size_t)p * B + b) * 2 + 0] = wpair[0];
            g_Zw[((size_t)p * B + b) * 2 + 1] = wpair[1];
            p++;
        }
    }
}

// sp-index offsets for the 20 (i, jj>=i/2) S pairs (matches precompute order)
__device__ __constant__ int POFF_[1]; // unused placeholder
#define POFF(i) ((i)==0?0:(i)==1?4:(i)==2?8:(i)==3?11:(i)==4?14:(i)==5?16:(i)==6?18:19)

// ---------------------------------------------------------------------------
// Warp-specialized flow kernel: threads [0,96) = velocity/trajectory role,
// threads [96,192) = rate (logJ) role, paired per batch element. 3 smem stage
// buffers (B, P1, P2); rate consumes stage s while vel builds s+1.
// Stage-state schedule: s0->B, s1->P1, s2->P2, s3->P1.
// RK4 combine without an accumulator:
//   slot2: Bslot <- (1/3)(U1 - B)        (after reading B for U3 = B + h k3)
//   slot3: Bslot <- Bpart + (2/3)U2 + (1/3)U3 + (h/6)k4  = U_{n+1}
// ---------------------------------------------------------------------------
__global__ __launch_bounds__(TPB, 2)
void flow_kernel(const float* __restrict__ U0,
                 const float* __restrict__ W0, const float* __restrict__ W1,
                 const float* __restrict__ W2, float* __restrict__ out, int B) {
    extern __shared__ char smem_raw[];
    ull*   sB    = reinterpret_cast<ull*>(smem_raw);     // base / new-base
    ull*   sP1   = sB  + 32 * ELEMS;
    ull*   sP2   = sP1 + 32 * ELEMS;
    ull*   sv    = sP2 + 32 * ELEMS;                     // eps pairs
    ull*   cW2aR = sv + 32 * ELEMS;                      // W2a row pairs [32]
    ull*   cW2aT = cW2aR + 32;                           // W2a col pairs [32]
    float* cw0a  = reinterpret_cast<float*>(cW2aT + 32);
    float* cw1a  = cw0a + 64;

    const int tid = threadIdx.x;
    const bool is_vel = (tid < ELEMS);
    const int col = is_vel ? tid : (tid - ELEMS);

    if (tid < 32) {
        int k = tid >> 2, cc = tid & 3;
        cW2aR[tid] = pack2(W2[k*8 + 2*cc]   - W2[(2*cc)*8 + k],
                           W2[k*8 + 2*cc+1] - W2[(2*cc+1)*8 + k]);
        int a = k;
        cW2aT[tid] = pack2(W2[(2*cc)*8 + a]   - W2[a*8 + 2*cc],
                           W2[(2*cc+1)*8 + a] - W2[a*8 + 2*cc + 1]);
    }
    if (tid < 64) {
        int i = tid >> 3, j = tid & 7;
        cw0a[tid] = 0.5f * (W0[i*8+j] - W0[j*8+i]);
        cw1a[tid] = 0.5f * (W1[i*8+j] - W1[j*8+i]);
    }

    int b = blockIdx.x * ELEMS + col;
    bool active = (b < B);
    int bb = active ? b : 0;

    if (is_vel) {
        // stage U0 into sB
        const ull* u0p = reinterpret_cast<const ull*>(U0) + (size_t)bb * 32;
#pragma unroll
        for (int p = 0; p < 32; p++)
            sB[p*ELEMS + col] = __ldg(u0p + p);
    } else {
        // stage eps pairs into sv
#pragma unroll
        for (int p = 0; p < 32; p++)
            sv[p*ELEMS + col] = __ldg(g_vp + (size_t)p * B + bb);
    }
    __syncthreads();

    const float dt = 1.0f / NSTEPS;
    const ull ZERO = 0ull;
    float lj = 0.f;
    const ull* zw = reinterpret_cast<const ull*>(g_Zw) + bb;

#pragma unroll 1
    for (int n = 0; n < NSTEPS; n++) {
        float tn = (float)n * dt;
#pragma unroll 1
        for (int s = 0; s < 4; s++) {
            const ull* cons = (s == 0) ? sB : ((s == 2) ? sP2 : sP1);

            if (is_vel) {
                // ---------------- VELOCITY ROLE ----------------
                float ts = tn + ((s == 0) ? 0.f : ((s == 3) ? dt : 0.5f * dt));
                ull Us[32];
#pragma unroll
                for (int p = 0; p < 32; p++) Us[p] = cons[p*ELEMS + col];

                // F = c01 + 0.5*(U W2a U^T), two half-passes over rows
                float F[28];
#pragma unroll
                for (int half = 0; half < 2; half++) {
                    const int i0 = half ? 4 : 0;
                    const int i1 = half ? 7 : 4;
                    ull P[16];
#pragma unroll
                    for (int t = 0; t < 16; t++) P[t] = ZERO;
#pragma unroll
                    for (int k = 0; k < 8; k++) {
                        ull w0 = cW2aR[k*4+0], w1 = cW2aR[k*4+1];
                        ull w2_ = cW2aR[k*4+2], w3 = cW2aR[k*4+3];
#pragma unroll
                        for (int i = i0; i < i1; i++) {
                            ull u = dup_elem(&Us[i*4], k);
                            P[(i-i0)*4+0] = f2fma(u, w0, P[(i-i0)*4+0]);
                            P[(i-i0)*4+1] = f2fma(u, w1, P[(i-i0)*4+1]);
                            P[(i-i0)*4+2] = f2fma(u, w2_, P[(i-i0)*4+2]);
                            P[(i-i0)*4+3] = f2fma(u, w3, P[(i-i0)*4+3]);
                        }
                    }
#pragma unroll
                    for (int i = i0; i < i1; i++) {
                        ull dacc[8];
#pragma unroll
                        for (int j = i + 1; j < 8; j++) dacc[j] = ZERO;
#pragma unroll
                        for (int cc = 0; cc < 4; cc++) {
#pragma unroll
                            for (int j = i + 1; j < 8; j++)
                                dacc[j] = f2fma(P[(i-i0)*4+cc], Us[j*4+cc], dacc[j]);
                        }
#pragma unroll
                        for (int j = i + 1; j < 8; j++) {
                            float c01 = fmaf(ts, cw1a[i*8+j], cw0a[i*8+j]);
                            F[fidx(i, j)] = fmaf(0.5f, hadd(dacc[j]), c01);
                        }
                    }
                }

                // velocity rows + stage combine (row-wise, immediate write)
                ull cH  = dupf(0.5f * dt);
                ull cF_ = dupf(dt);
                ull c13 = dupf(1.0f / 3.0f);
                ull c23 = dupf(2.0f / 3.0f);
                ull c16 = dupf(dt / 6.0f);
                ull NEG1 = dupf(-1.0f);
#pragma unroll
                for (int i = 0; i < 8; i++) {
                    ull v0 = ZERO, v1 = ZERO, v2_ = ZERO, v3 = ZERO;
#pragma unroll
                    for (int k = 0; k < 8; k++) {
                        if (k == i) continue;
                        float fs = (k > i) ? F[fidx(i, k)] : -F[fidx(k, i)];
                        ull fd = dupf(fs);
                        v0 = f2fma(fd, Us[k*4+0], v0);
                        v1 = f2fma(fd, Us[k*4+1], v1);
                        v2_ = f2fma(fd, Us[k*4+2], v2_);
                        v3 = f2fma(fd, Us[k*4+3], v3);
                    }
                    ull vr[4] = {v0, v1, v2_, v3};
#pragma unroll
                    for (int cc = 0; cc < 4; cc++) {
                        int idx = (i*4 + cc) * ELEMS + col;
                        if (s == 0) {
                            sP1[idx] = f2fma(cH, vr[cc], Us[i*4+cc]);
                        } else if (s == 1) {
                            ull bv = sB[idx];
                            sP2[idx] = f2fma(cH, vr[cc], bv);
                        } else if (s == 2) {
                            ull u1 = sP1[idx];
                            ull bv = sB[idx];
                            sP1[idx] = f2fma(cF_, vr[cc], bv);        // U3
                            ull d = f2fma(bv, NEG1, u1);              // U1 - B
                            sB[idx] = f2fma(d, c13, ZERO);            // partial
                        } else {
                            ull part = sB[idx];
                            ull u2 = sP2[idx];
                            ull t = f2fma(u2, c23, part);
                            t = f2fma(Us[i*4+cc], c13, t);
                            t = f2fma(vr[cc], c16, t);
                            sB[idx] = t;                              // U_{n+1}
                        }
                    }
                }
            } else {
                // ---------------- RATE ROLE ----------------
                // Q = v^T Us and S-pair partials, fused over streamed rows
                ull Q[32], sp[20];
#pragma unroll
                for (int p = 0; p < 32; p++) Q[p] = ZERO;
#pragma unroll
                for (int p = 0; p < 20; p++) sp[p] = ZERO;
#pragma unroll
                for (int k = 0; k < 8; k++) {
                    ull ur[4], vr[4];
#pragma unroll
                    for (int jj = 0; jj < 4; jj++) {
                        ur[jj] = cons[(k*4+jj)*ELEMS + col];
                        vr[jj] = sv[(k*4+jj)*ELEMS + col];
                    }
#pragma unroll
                    for (int d = 0; d < 8; d++) {
                        ull vd = dup_elem(vr, d);
#pragma unroll
                        for (int cc = 0; cc < 4; cc++)
                            Q[d*4+cc] = f2fma(vd, ur[cc], Q[d*4+cc]);
                    }
#pragma unroll
                    for (int i = 0; i < 8; i++) {
                        ull ud = dup_elem(ur, i);
#pragma unroll
                        for (int jj = 0; jj < 4; jj++) {
                            if (jj < i / 2) continue;
                            int p = POFF(i) + jj - i / 2;
                            sp[p] = f2fma(ud, ur[jj], sp[p]);
                        }
                    }
                }

                // r2 = tr(Q^2 W2a), G rows streamed
                ull r2p0 = ZERO, r2p1 = ZERO;
#pragma unroll
                for (int i = 0; i < 8; i++) {
                    ull g0 = ZERO, g1 = ZERO, g2 = ZERO, g3 = ZERO;
#pragma unroll
                    for (int k = 0; k < 8; k++) {
                        ull qd = dup_elem(&Q[i*4], k);
                        g0 = f2fma(qd, Q[k*4+0], g0);
                        g1 = f2fma(qd, Q[k*4+1], g1);
                        g2 = f2fma(qd, Q[k*4+2], g2);
                        g3 = f2fma(qd, Q[k*4+3], g3);
                    }
                    r2p0 = f2fma(g0, cW2aT[i*4+0], r2p0);
                    r2p1 = f2fma(g1, cW2aT[i*4+1], r2p1);
                    r2p0 = f2fma(g2, cW2aT[i*4+2], r2p0);
                    r2p1 = f2fma(g3, cW2aT[i*4+3], r2p1);
                }

                // r1 = <S pairs, Zw>
                ull r1p = ZERO;
#pragma unroll
                for (int p = 0; p < 20; p++)
                    r1p = f2fma(sp[p], __ldg(zw + (size_t)p * B), r1p);

                float rate = 0.5f * (hadd(r1p) + hadd(r2p0) + hadd(r2p1));
                float w = dt * ((s == 0 || s == 3) ? (1.f/6.f) : (1.f/3.f));
                lj = fmaf(w, rate, lj);
            }
            __syncthreads();
        }
    }

    if (active) {
        if (is_vel) {
            ull* outp = reinterpret_cast<ull*>(out) + (size_t)b * 32;
#pragma unroll
            for (int p = 0; p < 32; p++) outp[p] = sB[p*ELEMS + col];
        } else {
            out[(size_t)B * 64 + b] = lj;
        }
    }
}

extern "C" void kernel_launch(void* const* d_in, const int* in_sizes, int n_in,
                              void* d_out, int out_size) {
    const float* U0  = (const float*)d_in[0];
    const float* eps = (const float*)d_in[1];
    const float* W0  = (const float*)d_in[2];
    const float* W1  = (const float*)d_in[3];
    const float* W2  = (const float*)d_in[4];
    float* out = (float*)d_out;

    int B = in_sizes[0] / 64;
    if (B > BMAX) B = BMAX;

    cudaFuncSetAttribute(flow_kernel,
                         cudaFuncAttributeMaxDynamicSharedMemorySize, SMEM_BYTES);

    int gridp = (B + 255) / 256;
    precompute_kernel<<<gridp, 256>>>(eps, W2, B);
    int grid = (B + ELEMS - 1) / ELEMS;
    flow_kernel<<<grid, TPB, SMEM_BYTES>>>(U0, W0, W1, W2, out, B);
}

// round 16
// speedup vs baseline: 1.7043x; 1.7043x over previous
#include <cuda_runtime.h>
#include <cstddef>

#define NSTEPS 16
#define BMAX   131072
#define TPB    128

typedef unsigned long long ull;

// Per-batch folded Z weights (20 ull pairs, layout p*B + b), L2-resident stream
__device__ float g_Zw[40 * BMAX];

// ---------------- f32x2 helpers ----------------
__device__ __forceinline__ ull f2fma(ull a, ull b, ull c) {
    ull d;
    asm("fma.rn.f32x2 %0, %1, %2, %3;" : "=l"(d) : "l"(a), "l"(b), "l"(c));
    return d;
}
__device__ __forceinline__ ull dupf(float s) {
    ull d; asm("mov.b64 %0, {%1, %1};" : "=l"(d) : "f"(s)); return d;
}
__device__ __forceinline__ ull dup_lo(ull p) {
    ull d;
    asm("{\n\t.reg .f32 l,h;\n\tmov.b64 {l,h}, %1;\n\tmov.b64 %0, {l,l};\n\t}"
        : "=l"(d) : "l"(p));
    return d;
}
__device__ __forceinline__ ull dup_hi(ull p) {
    ull d;
    asm("{\n\t.reg .f32 l,h;\n\tmov.b64 {l,h}, %1;\n\tmov.b64 %0, {h,h};\n\t}"
        : "=l"(d) : "l"(p));
    return d;
}
__device__ __forceinline__ float hadd(ull p) {
    float l, h; asm("mov.b64 {%0, %1}, %2;" : "=f"(l), "=f"(h) : "l"(p)); return l + h;
}
__device__ __forceinline__ ull pack2(float a, float b) {
    ull d; asm("mov.b64 %0, {%1, %2};" : "=l"(d) : "f"(a), "f"(b)); return d;
}
// dup of element k of a pair-array row (pairs base[0..3] hold cols 0..7)
__device__ __forceinline__ ull dup_elem(const ull* base, int k) {
    return (k & 1) ? dup_hi(base[k >> 1]) : dup_lo(base[k >> 1]);
}

__device__ __forceinline__ constexpr int fidx(int i, int j) {
    return i * 8 - i * (i + 1) / 2 + (j - i - 1);
}

// smem per CTA: sUb[32*TPB] + sacc[32*TPB] + sv[32*TPB] (all ull) + weights
#define SMEM_BYTES (3*32*TPB*8 + 64*8 + 128*4)

// ---------------------------------------------------------------------------
// Precompute per-batch folded Z = C W2 - W2 C weights (C = v^T v),
// packed for the 20 (i, jpair) S-pairs, transposed layout p*B + b.
// ---------------------------------------------------------------------------
__global__ void precompute_kernel(const float* __restrict__ eps,
                                  const float* __restrict__ W2, int B) {
    int b = blockIdx.x * blockDim.x + threadIdx.x;
    if (b >= B) return;

    float v[64];
    const float4* vp = reinterpret_cast<const float4*>(eps + (size_t)b * 64);
#pragma unroll
    for (int i = 0; i < 16; i++) {
        float4 t = __ldg(vp + i);
        v[4*i+0] = t.x; v[4*i+1] = t.y; v[4*i+2] = t.z; v[4*i+3] = t.w;
    }

    float C[8][8];
#pragma unroll
    for (int i = 0; i < 8; i++) {
#pragma unroll
        for (int j = i; j < 8; j++) {
            float s = 0.f;
#pragma unroll
            for (int k = 0; k < 8; k++) s = fmaf(v[k*8+i], v[k*8+j], s);
            C[i][j] = s; C[j][i] = s;
        }
    }

    float w2a[8][8];
#pragma unroll
    for (int i = 0; i < 8; i++)
#pragma unroll
        for (int j = 0; j < 8; j++)
            w2a[i][j] = __ldg(W2 + i*8 + j) - __ldg(W2 + j*8 + i);

    int p = 0;
#pragma unroll
    for (int i = 0; i < 8; i++) {
#pragma unroll
        for (int jj = 0; jj < 4; jj++) {
            if (jj < i / 2) continue;
            float wpair[2];
#pragma unroll
            for (int h = 0; h < 2; h++) {
                int j = 2*jj + h;
                float s = 0.f;
                if (j > i) {
#pragma unroll
                    for (int k = 0; k < 8; k++)
                        s -= C[i][k] * w2a[j][k] + C[j][k] * w2a[i][k];
                } else if (j == i) {
#pragma unroll
                    for (int k = 0; k < 8; k++) s -= C[i][k] * w2a[i][k];
                }
                wpair[h] = s;
            }
            g_Zw[((size_t)p * B + b) * 2 + 0] = wpair[0];
            g_Zw[((size_t)p * B + b) * 2 + 1] = wpair[1];
            p++;
        }
    }
}

// ---------------------------------------------------------------------------
// One RK4 stage, fully compile-time specialized (S = 0..3).
// TS_OFF, W, CC fold to immediates; branches vanish.
// ---------------------------------------------------------------------------
#define DO_STAGE(S)                                                            \
do {                                                                           \
    const float TS_OFF = (S == 0) ? 0.f                                        \
                       : (S == 3) ? (1.0f / NSTEPS) : (0.5f / NSTEPS);         \
    const float W_  = (S == 0 || S == 3) ? (1.0f / (6 * NSTEPS))               \
                                         : (1.0f / (3 * NSTEPS));              \
    const float CC_ = (S == 2) ? (1.0f / NSTEPS) : (0.5f / NSTEPS);            \
    float ts = tn + TS_OFF;                                                    \
    /* Q = v^T Us */                                                           \
    ull Q[32];                                                                 \
    _Pragma("unroll")                                                          \
    for (int p = 0; p < 32; p++) Q[p] = ZERO;                                  \
    _Pragma("unroll")                                                          \
    for (int k = 0; k < 8; k++) {                                              \
        ull vp0 = sv[(k*4+0)*TPB + tid], vp1 = sv[(k*4+1)*TPB + tid];          \
        ull vp2 = sv[(k*4+2)*TPB + tid], vp3 = sv[(k*4+3)*TPB + tid];          \
        ull vd[8];                                                             \
        vd[0] = dup_lo(vp0); vd[1] = dup_hi(vp0);                              \
        vd[2] = dup_lo(vp1); vd[3] = dup_hi(vp1);                              \
        vd[4] = dup_lo(vp2); vd[5] = dup_hi(vp2);                              \
        vd[6] = dup_lo(vp3); vd[7] = dup_hi(vp3);                              \
        _Pragma("unroll")                                                      \
        for (int cc = 0; cc < 4; cc++) {                                       \
            _Pragma("unroll")                                                  \
            for (int d = 0; d < 8; d++)                                        \
                Q[d*4+cc] = f2fma(vd[d], Us[k*4+cc], Q[d*4+cc]);               \
        }                                                                      \
    }                                                                          \
    /* G = Q*Q then r2 = tr(G W2a) */                                          \
    ull r2p0 = ZERO, r2p1 = ZERO;                                              \
    {                                                                          \
        ull G[32];                                                             \
        _Pragma("unroll")                                                      \
        for (int p = 0; p < 32; p++) G[p] = ZERO;                              \
        _Pragma("unroll")                                                      \
        for (int k = 0; k < 8; k++) {                                          \
            ull qd[8];                                                         \
            _Pragma("unroll")                                                  \
            for (int i = 0; i < 8; i++) qd[i] = dup_elem(&Q[i*4], k);          \
            _Pragma("unroll")                                                  \
            for (int cc = 0; cc < 4; cc++) {                                   \
                _Pragma("unroll")                                              \
                for (int i = 0; i < 8; i++)                                    \
                    G[i*4+cc] = f2fma(qd[i], Q[k*4+cc], G[i*4+cc]);            \
            }                                                                  \
        }                                                                      \
        _Pragma("unroll")                                                      \
        for (int a = 0; a < 8; a++) {                                          \
            _Pragma("unroll")                                                  \
            for (int cp = 0; cp < 4; cp++) {                                   \
                if ((a ^ cp) & 1)                                              \
                    r2p1 = f2fma(G[a*4+cp], cW2aT[a*4+cp], r2p1);              \
                else                                                           \
                    r2p0 = f2fma(G[a*4+cp], cW2aT[a*4+cp], r2p0);              \
            }                                                                  \
        }                                                                      \
    }                                                                          \
    /* r1 = <U^T U folded pairs, Zw> */                                        \
    ull r1p = ZERO;                                                            \
    {                                                                          \
        int p = 0;                                                             \
        _Pragma("unroll")                                                      \
        for (int i = 0; i < 8; i++) {                                          \
            ull duds[8];                                                       \
            _Pragma("unroll")                                                  \
            for (int k = 0; k < 8; k++)                                        \
                duds[k] = dup_elem(&Us[k*4], i);                               \
            ull sp[4];                                                         \
            _Pragma("unroll")                                                  \
            for (int jj = 0; jj < 4; jj++) sp[jj] = ZERO;                      \
            _Pragma("unroll")                                                  \
            for (int k = 0; k < 8; k++) {                                      \
                _Pragma("unroll")                                              \
                for (int jj = 0; jj < 4; jj++) {                               \
                    if (jj < i / 2) continue;                                  \
                    sp[jj] = f2fma(duds[k], Us[k*4+jj], sp[jj]);               \
                }                                                              \
            }                                                                  \
            _Pragma("unroll")                                                  \
            for (int jj = 0; jj < 4; jj++) {                                   \
                if (jj < i / 2) continue;                                      \
                ull z = __ldg(zw + (size_t)p * B);                             \
                r1p = f2fma(sp[jj], z, r1p);                                   \
                p++;                                                           \
            }                                                                  \
        }                                                                      \
    }                                                                          \
    float rate = 0.5f * (hadd(r1p) + hadd(r2p0) + hadd(r2p1));                 \
    /* F phase */                                                              \
    float F[28];                                                               \
    {                                                                          \
        ull wreg[32];                                                          \
        _Pragma("unroll")                                                      \
        for (int t = 0; t < 32; t++) wreg[t] = cW2aR[t];                       \
        _Pragma("unroll")                                                      \
        for (int i = 0; i < 7; i++) {                                          \
            ull P[4];                                                          \
            _Pragma("unroll")                                                  \
            for (int cc = 0; cc < 4; cc++) P[cc] = ZERO;                       \
            _Pragma("unroll")                                                  \
            for (int k = 0; k < 8; k++) {                                      \
                ull u = dup_elem(&Us[i*4], k);                                 \
                _Pragma("unroll")                                              \
                for (int cc = 0; cc < 4; cc++)                                 \
                    P[cc] = f2fma(u, wreg[k*4+cc], P[cc]);                     \
            }                                                                  \
            ull dacc[8];                                                       \
            _Pragma("unroll")                                                  \
            for (int j = i + 1; j < 8; j++) dacc[j] = ZERO;                    \
            _Pragma("unroll")                                                  \
            for (int cc = 0; cc < 4; cc++) {                                   \
                _Pragma("unroll")                                              \
                for (int j = i + 1; j < 8; j++)                                \
                    dacc[j] = f2fma(P[cc], Us[j*4+cc], dacc[j]);               \
            }                                                                  \
            _Pragma("unroll")                                                  \
            for (int j = i + 1; j < 8; j++) {                                  \
                float c01 = fmaf(ts, cw1a[i*8+j], cw0a[i*8+j]);                \
                F[fidx(i, j)] = fmaf(0.5f, hadd(dacc[j]), c01);                \
            }                                                                  \
        }                                                                      \
    }                                                                          \
    /* vel = F * Us */                                                         \
    ull vel[32];                                                               \
    _Pragma("unroll")                                                          \
    for (int p = 0; p < 32; p++) vel[p] = ZERO;                                \
    _Pragma("unroll")                                                          \
    for (int k = 0; k < 8; k++) {                                              \
        ull fd[8];                                                             \
        _Pragma("unroll")                                                      \
        for (int i = 0; i < 8; i++) {                                          \
            if (i == k) continue;                                              \
            float fs = (k > i) ? F[fidx(i, k)] : -F[fidx(k, i)];               \
            fd[i] = dupf(fs);                                                  \
        }                                                                      \
        _Pragma("unroll")                                                      \
        for (int cc = 0; cc < 4; cc++) {                                       \
            _Pragma("unroll")                                                  \
            for (int i = 0; i < 8; i++) {                                      \
                if (i == k) continue;                                          \
                vel[i*4+cc] = f2fma(fd[i], Us[k*4+cc], vel[i*4+cc]);           \
            }                                                                  \
        }                                                                      \
    }                                                                          \
    /* RK4 combine (constants folded) */                                       \
    lj = fmaf(W_, rate, lj);                                                   \
    ull wd = dupf(W_);                                                         \
    ull cd = dupf(CC_);                                                        \
    _Pragma("unroll")                                                          \
    for (int p = 0; p < 32; p++) {                                             \
        ull ac = f2fma(wd, vel[p], sacc[p*TPB + tid]);                         \
        sacc[p*TPB + tid] = ac;                                                \
        Us[p] = (S < 3) ? f2fma(cd, vel[p], sUb[p*TPB + tid]) : ac;            \
    }                                                                          \
} while (0)

// ---------------------------------------------------------------------------
// Main flow kernel: R11 structure with the 4-stage loop fully unrolled via
// DO_STAGE so stage coefficients fold to immediates and stage boundaries
// become straight-line code.
// ---------------------------------------------------------------------------
__global__ __launch_bounds__(TPB, 2)
void flow_kernel(const float* __restrict__ U0, const float* __restrict__ eps,
                 const float* __restrict__ W0, const float* __restrict__ W1,
                 const float* __restrict__ W2, float* __restrict__ out, int B) {
    extern __shared__ char smem_raw[];
    ull*   sUb   = reinterpret_cast<ull*>(smem_raw);
    ull*   sacc  = sUb + 32 * TPB;
    ull*   sv    = sacc + 32 * TPB;   // eps pairs [pair][tid]
    ull*   cW2aR = sv + 32 * TPB;     // W2a row pairs [32]
    ull*   cW2aT = cW2aR + 32;        // W2a col pairs [32]
    float* cw0a  = reinterpret_cast<float*>(cW2aT + 32);
    float* cw1a  = cw0a + 64;

    const int tid = threadIdx.x;

    if (tid < 32) {
        int k = tid >> 2, cc = tid & 3;
        cW2aR[tid] = pack2(W2[k*8 + 2*cc]   - W2[(2*cc)*8 + k],
                           W2[k*8 + 2*cc+1] - W2[(2*cc+1)*8 + k]);
        int a = k;
        cW2aT[tid] = pack2(W2[(2*cc)*8 + a]   - W2[a*8 + 2*cc],
                           W2[(2*cc+1)*8 + a] - W2[a*8 + 2*cc + 1]);
    }
    if (tid < 64) {
        int i = tid >> 3, j = tid & 7;
        cw0a[tid] = 0.5f * (W0[i*8+j] - W0[j*8+i]);
        cw1a[tid] = 0.5f * (W1[i*8+j] - W1[j*8+i]);
    }

    int b = blockIdx.x * TPB + tid;
    bool active = (b < B);
    int bb = active ? b : 0;

    ull Us[32];
    {
        const ull* u0p = reinterpret_cast<const ull*>(U0) + (size_t)bb * 32;
        const ull* evp = reinterpret_cast<const ull*>(eps) + (size_t)bb * 32;
#pragma unroll
        for (int p = 0; p < 32; p++) {
            ull u = __ldg(u0p + p);
            Us[p] = u;
            sUb[p*TPB + tid]  = u;
            sacc[p*TPB + tid] = u;
            sv[p*TPB + tid]   = __ldg(evp + p);
        }
    }
    __syncthreads();

    float lj = 0.f;
    const float dt = 1.0f / NSTEPS;
    const ull* zw = reinterpret_cast<const ull*>(g_Zw) + bb;
    const ull ZERO = 0ull;

#pragma unroll 1
    for (int n = 0; n < NSTEPS; n++) {
        float tn = (float)n * dt;

        DO_STAGE(0);
        DO_STAGE(1);
        DO_STAGE(2);
        DO_STAGE(3);

#pragma unroll
        for (int p = 0; p < 32; p++) sUb[p*TPB + tid] = Us[p];
    }

    if (active) {
        ull* outp = reinterpret_cast<ull*>(out) + (size_t)b * 32;
#pragma unroll
        for (int p = 0; p < 32; p++) outp[p] = Us[p];
        out[(size_t)B * 64 + b] = lj;
    }
}

extern "C" void kernel_launch(void* const* d_in, const int* in_sizes, int n_in,
                              void* d_out, int out_size) {
    const float* U0  = (const float*)d_in[0];
    const float* eps = (const float*)d_in[1];
    const float* W0  = (const float*)d_in[2];
    const float* W1  = (const float*)d_in[3];
    const float* W2  = (const float*)d_in[4];
    float* out = (float*)d_out;

    int B = in_sizes[0] / 64;
    if (B > BMAX) B = BMAX;

    cudaFuncSetAttribute(flow_kernel,
                         cudaFuncAttributeMaxDynamicSharedMemorySize, SMEM_BYTES);

    int gridp = (B + 255) / 256;
    precompute_kernel<<<gridp, 256>>>(eps, W2, B);
    int grid = (B + TPB - 1) / TPB;
    flow_kernel<<<grid, TPB, SMEM_BYTES>>>(U0, eps, W0, W1, W2, out, B);
}